// round 4
// baseline (speedup 1.0000x reference)
#include <cuda_runtime.h>
#include <cuda_bf16.h>
#include <cstdint>

#define B 512
#define T 256
#define C 384
#define HS 64
#define BT (B * T)

// ---------------- scratch -----------------------------------------------------
__device__ float g_Q[BT * HS];
__device__ float g_K[BT * HS];
__device__ float g_V[BT * HS];

// ---------------- f32x2 helpers ------------------------------------------------
__device__ __forceinline__ void fma2(uint64_t& d, uint64_t a, uint64_t b) {
    asm("fma.rn.f32x2 %0, %1, %2, %0;" : "+l"(d) : "l"(a), "l"(b));
}
__device__ __forceinline__ uint64_t pack2(float lo, float hi) {
    uint64_t r;
    asm("mov.b64 %0, {%1, %2};" : "=l"(r) : "f"(lo), "f"(hi));
    return r;
}
__device__ __forceinline__ void unpack2(uint64_t v, float& lo, float& hi) {
    asm("mov.b64 {%0, %1}, %2;" : "=f"(lo), "=f"(hi) : "l"(v));
}
__device__ __forceinline__ uint32_t smem_u32(const void* p) {
    uint32_t a;
    asm("{ .reg .u64 t; cvta.to.shared.u64 t, %1; cvt.u32.u64 %0, t; }"
        : "=r"(a) : "l"(p));
    return a;
}
__device__ __forceinline__ void lds_v2u64(uint64_t& a, uint64_t& b, uint32_t addr) {
    asm volatile("ld.shared.v2.b64 {%0, %1}, [%2];" : "=l"(a), "=l"(b) : "r"(addr));
}

// ---------------- fused QKV GEMM: O[BT,192] = X[BT,384] @ [Wq|Wk|Wv] ----------
// 256 threads, CTA tile 128x192, BK=32. Thread tile 8 rows x 12 cols (6 f32x2).
__global__ __launch_bounds__(256) void qkv_gemm(
    const float* __restrict__ x,
    const float* __restrict__ Wq,
    const float* __restrict__ Wk,
    const float* __restrict__ Wv)
{
    __shared__ float xs[128][32];
    __shared__ float ws[32][192];

    const int tid  = threadIdx.x;
    const int tcol = tid & 15;   // 16 col-groups * 12 cols = 192
    const int trow = tid >> 4;   // 16 row-groups * 8 rows  = 128
    const int rowBase = blockIdx.x * 128;

    uint64_t acc[8][6];
#pragma unroll
    for (int r = 0; r < 8; r++)
#pragma unroll
        for (int c = 0; c < 6; c++) acc[r][c] = 0ull;

    const uint32_t xs_base = smem_u32(&xs[0][0]);
    const uint32_t ws_base = smem_u32(&ws[0][0]);

    for (int k0 = 0; k0 < C; k0 += 32) {
        // x tile: 128x32 = 1024 float4, 4 per thread
#pragma unroll
        for (int t = 0; t < 4; t++) {
            int f = tid + t * 256;
            int r = f >> 3;
            int c4 = f & 7;
            *(float4*)(&xs[r][c4 * 4]) =
                *(const float4*)(x + (size_t)(rowBase + r) * C + k0 + c4 * 4);
        }
        // W tile: 32x192 = 1536 float4, 6 per thread; 48 float4 per row
#pragma unroll
        for (int t = 0; t < 6; t++) {
            int f = tid + t * 256;
            int r = f / 48;
            int u = f - r * 48;
            const float* W = (u < 16) ? Wq : ((u < 32) ? Wk : Wv);
            *(float4*)(&ws[r][u * 4]) =
                *(const float4*)(W + (size_t)(k0 + r) * HS + ((u & 15) << 2));
        }
        __syncthreads();

#pragma unroll
        for (int kk = 0; kk < 32; kk++) {
            uint64_t a2[8];
#pragma unroll
            for (int r = 0; r < 8; r++) {
                float av = xs[trow * 8 + r][kk];
                a2[r] = pack2(av, av);
            }
            uint64_t b2[6];
            {
                uint32_t baddr = ws_base + ((uint32_t)kk * 192 + (uint32_t)tcol * 12) * 4;
                lds_v2u64(b2[0], b2[1], baddr);
                lds_v2u64(b2[2], b2[3], baddr + 16);
                lds_v2u64(b2[4], b2[5], baddr + 32);
            }
#pragma unroll
            for (int r = 0; r < 8; r++)
#pragma unroll
                for (int c = 0; c < 6; c++)
                    fma2(acc[r][c], a2[r], b2[c]);
        }
        __syncthreads();
    }
    (void)xs_base;

    // epilogue: cols [0,64)->Q, [64,128)->K, [128,192)->V
#pragma unroll
    for (int r = 0; r < 8; r++) {
        int row = rowBase + trow * 8 + r;
#pragma unroll
        for (int c = 0; c < 6; c++) {
            int col = tcol * 12 + c * 2;
            float* dst = (col < 64) ? g_Q : ((col < 128) ? g_K : g_V);
            int cc = col & 63;
            float lo, hi;
            unpack2(acc[r][c], lo, hi);
            *(float2*)(dst + (size_t)row * HS + cc) = make_float2(lo, hi);
        }
    }
}

// ---------------- causal attention: one CTA per batch, f32x2 ------------------
__global__ __launch_bounds__(256, 1) void attn(float* __restrict__ out)
{
    extern __shared__ float smemf[];
    float4* ks4 = (float4*)smemf;                // 256x64 = 16384 floats
    float4* vs4 = (float4*)(smemf + T * HS);

    const int b   = blockIdx.x;
    const int tid = threadIdx.x;

    const float4* Kg = (const float4*)(g_K + (size_t)b * T * HS);
    const float4* Vg = (const float4*)(g_V + (size_t)b * T * HS);
#pragma unroll
    for (int t = 0; t < 16; t++) {
        ks4[tid + t * 256] = Kg[tid + t * 256];
        vs4[tid + t * 256] = Vg[tid + t * 256];
    }
    __syncthreads();

    const uint32_t ks_base = smem_u32(ks4);
    const uint32_t vs_base = smem_u32(vs4);

    const int i = tid;  // query row
    uint64_t q2[32];
    {
        const float* Qg = g_Q + ((size_t)b * T + i) * HS;
#pragma unroll
        for (int h = 0; h < 32; h++)
            q2[h] = pack2(Qg[2 * h], Qg[2 * h + 1]);
    }

    uint64_t acc2[32];
#pragma unroll
    for (int h = 0; h < 32; h++) acc2[h] = 0ull;
    float l = 0.0f;
    const float scale = 0.125f;            // HS^-0.5
    const float log2e_scale = 1.4426950408889634f * scale;

    for (int j = 0; j <= i; j++) {
        // ---- dot(q, k_j) in f32x2, 4 split accumulators ----
        uint32_t krow = ks_base + (uint32_t)j * 256;
        uint64_t s2[4] = {0ull, 0ull, 0ull, 0ull};
#pragma unroll
        for (int h = 0; h < 16; h++) {
            uint64_t k0, k1;
            lds_v2u64(k0, k1, krow + h * 16);
            fma2(s2[(2 * h) & 3], q2[2 * h], k0);
            fma2(s2[(2 * h + 1) & 3], q2[2 * h + 1], k1);
        }
        float a0, a1, b0, b1, c0, c1, d0, d1;
        unpack2(s2[0], a0, a1);
        unpack2(s2[1], b0, b1);
        unpack2(s2[2], c0, c1);
        unpack2(s2[3], d0, d1);
        float s = ((a0 + a1) + (b0 + b1)) + ((c0 + c1) + (d0 + d1));
        // exp(s*scale) = 2^(s*scale*log2e)
        float p;
        asm("ex2.approx.f32 %0, %1;" : "=f"(p) : "f"(s * log2e_scale));
        l += p;
        uint64_t p2 = pack2(p, p);

        // ---- acc += p * v_j ----
        uint32_t vrow = vs_base + (uint32_t)j * 256;
#pragma unroll
        for (int h = 0; h < 16; h++) {
            uint64_t v0, v1;
            lds_v2u64(v0, v1, vrow + h * 16);
            fma2(acc2[2 * h], p2, v0);
            fma2(acc2[2 * h + 1], p2, v1);
        }
    }

    const float inv = 1.0f / l;
    float* og = out + ((size_t)b * T + i) * HS;
#pragma unroll
    for (int h = 0; h < 16; h++) {
        float e0, e1, e2, e3;
        unpack2(acc2[2 * h], e0, e1);
        unpack2(acc2[2 * h + 1], e2, e3);
        *(float4*)(og + 4 * h) = make_float4(e0 * inv, e1 * inv, e2 * inv, e3 * inv);
    }
}

// ---------------- launch -------------------------------------------------------
extern "C" void kernel_launch(void* const* d_in, const int* in_sizes, int n_in,
                              void* d_out, int out_size)
{
    (void)in_sizes; (void)n_in; (void)out_size;
    const float* x  = (const float*)d_in[0];
    const float* Wq = (const float*)d_in[1];
    const float* Wk = (const float*)d_in[2];
    const float* Wv = (const float*)d_in[3];
    float* out = (float*)d_out;

    qkv_gemm<<<BT / 128, 256>>>(x, Wq, Wk, Wv);

    const int attn_smem = 2 * T * HS * sizeof(float);  // 128 KB
    cudaFuncSetAttribute(attn, cudaFuncAttributeMaxDynamicSharedMemorySize,
                         attn_smem);
    attn<<<B, 256, attn_smem>>>(out);
}

// round 6
// speedup vs baseline: 1.5058x; 1.5058x over previous
#include <cuda_runtime.h>
#include <cuda_bf16.h>
#include <mma.h>
#include <cstdint>

using namespace nvcuda;

#define B 512
#define T 256
#define C 384
#define HS 64
#define BT (B * T)

// ---------------- scratch -----------------------------------------------------
__device__ float g_Q[BT * HS];
__device__ float g_K[BT * HS];
__device__ float g_V[BT * HS];
// bf16 split weights, [k][n] row-major, n in [0,192) = [Wq|Wk|Wv] columns
__device__ __nv_bfloat16 g_Whi[C * 192];
__device__ __nv_bfloat16 g_Wlo[C * 192];

// ---------------- W bf16 split kernel ------------------------------------------
__global__ void convert_w(const float* __restrict__ Wq,
                          const float* __restrict__ Wk,
                          const float* __restrict__ Wv)
{
    int k = blockIdx.x;     // 0..383
    int n = threadIdx.x;    // 0..191
    const float* W = (n < 64) ? Wq : ((n < 128) ? Wk : Wv);
    float w = W[(size_t)k * HS + (n & 63)];
    __nv_bfloat16 hi = __float2bfloat16(w);
    __nv_bfloat16 lo = __float2bfloat16(w - __bfloat162float(hi));
    g_Whi[(size_t)k * 192 + n] = hi;
    g_Wlo[(size_t)k * 192 + n] = lo;
}

// ---------------- QKV GEMM: WMMA bf16 3-product split, double-buffered --------
// 512 threads = 16 warps (4M x 4N). CTA tile 128x192, BK=32, 12 chunks.
// smem per stage: Ahi/Alo [128][40] bf16, Bhi/Blo [32][200] bf16.
static constexpr int A_LD = 40;
static constexpr int B_LD = 200;
static constexpr int OFF_AHI = 0;          // 128*40*2 = 10240
static constexpr int OFF_ALO = 10240;
static constexpr int OFF_BHI = 20480;      // 32*200*2 = 12800
static constexpr int OFF_BLO = 33280;
static constexpr int STAGE   = 46080;
static constexpr int GEMM_SMEM_TOTAL = 2 * STAGE;   // 92160

__global__ __launch_bounds__(512) void qkv_gemm_wmma(const float* __restrict__ x)
{
    extern __shared__ char smem[];
    const int tid = threadIdx.x;
    const int wid = tid >> 5;
    const int warp_m = wid >> 2;       // 0..3 -> rows 32*warp_m
    const int warp_n = wid & 3;        // 0..3 -> cols 48*warp_n
    const int rowBase = blockIdx.x * 128;

    wmma::fragment<wmma::accumulator, 16, 16, 16, float> acc[2][3];
#pragma unroll
    for (int i = 0; i < 2; i++)
#pragma unroll
        for (int j = 0; j < 3; j++) wmma::fill_fragment(acc[i][j], 0.0f);

    // ---- prologue: chunk 0 into stage 0 ----
    {
        char* st = smem;
#pragma unroll
        for (int t = 0; t < 2; t++) {
            int f = tid + t * 512;
            int r = f >> 3, c4 = f & 7;
            float4 v = *(const float4*)(x + (size_t)(rowBase + r) * C + c4 * 4);
            __nv_bfloat16* ah = (__nv_bfloat16*)(st + OFF_AHI) + r * A_LD + c4 * 4;
            __nv_bfloat16* al = (__nv_bfloat16*)(st + OFF_ALO) + r * A_LD + c4 * 4;
            ah[0] = __float2bfloat16(v.x);
            ah[1] = __float2bfloat16(v.y);
            ah[2] = __float2bfloat16(v.z);
            ah[3] = __float2bfloat16(v.w);
            al[0] = __float2bfloat16(v.x - __bfloat162float(ah[0]));
            al[1] = __float2bfloat16(v.y - __bfloat162float(ah[1]));
            al[2] = __float2bfloat16(v.z - __bfloat162float(ah[2]));
            al[3] = __float2bfloat16(v.w - __bfloat162float(ah[3]));
        }
#pragma unroll
        for (int t = 0; t < 3; t++) {
            int f = tid + t * 512;                // 0..1535
            int g = (f < 768) ? f : (f - 768);    // FIXED: 768 is not pow2
            int r = g / 24, u = g - r * 24;
            const __nv_bfloat16* src = (f < 768) ? g_Whi : g_Wlo;
            int dstOff = (f < 768) ? OFF_BHI : OFF_BLO;
            *(uint4*)(st + dstOff + (r * B_LD + u * 8) * 2) =
                *(const uint4*)(src + (size_t)r * 192 + u * 8);
        }
    }
    __syncthreads();

    for (int c = 0; c < 12; c++) {
        char* st = smem + (c & 1) * STAGE;
        char* nst = smem + ((c + 1) & 1) * STAGE;
        const int k1 = (c + 1) * 32;
        const bool more = (c + 1 < 12);

        // global prefetch of chunk c+1
        float4 xr[2];
        uint4 wr[3];
        if (more) {
#pragma unroll
            for (int t = 0; t < 2; t++) {
                int f = tid + t * 512;
                int r = f >> 3, c4 = f & 7;
                xr[t] = *(const float4*)(x + (size_t)(rowBase + r) * C + k1 + c4 * 4);
            }
#pragma unroll
            for (int t = 0; t < 3; t++) {
                int f = tid + t * 512;
                int g = (f < 768) ? f : (f - 768);   // FIXED
                int r = g / 24, u = g - r * 24;
                const __nv_bfloat16* src = (f < 768) ? g_Whi : g_Wlo;
                wr[t] = *(const uint4*)(src + (size_t)(k1 + r) * 192 + u * 8);
            }
        }

        // compute chunk c
        const __nv_bfloat16* Ahi = (const __nv_bfloat16*)(st + OFF_AHI);
        const __nv_bfloat16* Alo = (const __nv_bfloat16*)(st + OFF_ALO);
        const __nv_bfloat16* Bhi = (const __nv_bfloat16*)(st + OFF_BHI);
        const __nv_bfloat16* Blo = (const __nv_bfloat16*)(st + OFF_BLO);
#pragma unroll
        for (int ks = 0; ks < 2; ks++) {
            wmma::fragment<wmma::matrix_a, 16, 16, 16, __nv_bfloat16, wmma::row_major> ah[2], al[2];
#pragma unroll
            for (int i = 0; i < 2; i++) {
                const __nv_bfloat16* pa = Ahi + (warp_m * 32 + i * 16) * A_LD + ks * 16;
                const __nv_bfloat16* pl = Alo + (warp_m * 32 + i * 16) * A_LD + ks * 16;
                wmma::load_matrix_sync(ah[i], pa, A_LD);
                wmma::load_matrix_sync(al[i], pl, A_LD);
            }
#pragma unroll
            for (int j = 0; j < 3; j++) {
                int col = warp_n * 48 + j * 16;
                wmma::fragment<wmma::matrix_b, 16, 16, 16, __nv_bfloat16, wmma::row_major> bh, bl;
                wmma::load_matrix_sync(bh, Bhi + ks * 16 * B_LD + col, B_LD);
                wmma::load_matrix_sync(bl, Blo + ks * 16 * B_LD + col, B_LD);
#pragma unroll
                for (int i = 0; i < 2; i++) {
                    wmma::mma_sync(acc[i][j], ah[i], bh, acc[i][j]);
                    wmma::mma_sync(acc[i][j], ah[i], bl, acc[i][j]);
                    wmma::mma_sync(acc[i][j], al[i], bh, acc[i][j]);
                }
            }
        }

        // store prefetched chunk into the other stage
        if (more) {
#pragma unroll
            for (int t = 0; t < 2; t++) {
                int f = tid + t * 512;
                int r = f >> 3, c4 = f & 7;
                __nv_bfloat16* ah = (__nv_bfloat16*)(nst + OFF_AHI) + r * A_LD + c4 * 4;
                __nv_bfloat16* al = (__nv_bfloat16*)(nst + OFF_ALO) + r * A_LD + c4 * 4;
                float4 v = xr[t];
                ah[0] = __float2bfloat16(v.x);
                ah[1] = __float2bfloat16(v.y);
                ah[2] = __float2bfloat16(v.z);
                ah[3] = __float2bfloat16(v.w);
                al[0] = __float2bfloat16(v.x - __bfloat162float(ah[0]));
                al[1] = __float2bfloat16(v.y - __bfloat162float(ah[1]));
                al[2] = __float2bfloat16(v.z - __bfloat162float(ah[2]));
                al[3] = __float2bfloat16(v.w - __bfloat162float(ah[3]));
            }
#pragma unroll
            for (int t = 0; t < 3; t++) {
                int f = tid + t * 512;
                int g = (f < 768) ? f : (f - 768);   // FIXED (index recompute)
                int r = g / 24, u = g - r * 24;
                int dstOff = (f < 768) ? OFF_BHI : OFF_BLO;
                *(uint4*)(nst + dstOff + (r * B_LD + u * 8) * 2) = wr[t];
            }
        }
        __syncthreads();
    }

    // epilogue
#pragma unroll
    for (int i = 0; i < 2; i++) {
#pragma unroll
        for (int j = 0; j < 3; j++) {
            int col = warp_n * 48 + j * 16;
            float* dst = (col < 64) ? g_Q : ((col < 128) ? g_K : g_V);
            int cc = col & 63;
            int row = rowBase + warp_m * 32 + i * 16;
            wmma::store_matrix_sync(dst + (size_t)row * HS + cc, acc[i][j], HS,
                                    wmma::mem_row_major);
        }
    }
}

// ---------------- causal attention v3: half-split, 512 threads/CTA ------------
// thread = (row tid>>1, half tid&1); each owns 32 dims; dot via shfl.xor(1).
// Loop bound made warp-uniform (row|15) so the full-mask shfl is defined.
static constexpr int KROW = 72;
static constexpr int ATTN_SMEM = 2 * T * KROW * 4;   // 147456

__global__ __launch_bounds__(512, 1) void attn(float* __restrict__ out)
{
    extern __shared__ float sm[];
    float* ks = sm;                 // [256][72]
    float* vs = sm + T * KROW;      // [256][72]

    const int b   = blockIdx.x;
    const int tid = threadIdx.x;
    const int row  = tid >> 1;
    const int half = tid & 1;

    // cooperative load: K,V each 256 rows x 16 float4; 4096 f4 per array
    {
        const float4* Kg = (const float4*)(g_K + (size_t)b * T * HS);
        const float4* Vg = (const float4*)(g_V + (size_t)b * T * HS);
#pragma unroll
        for (int t = 0; t < 8; t++) {
            int f = tid + t * 512;
            int j = f >> 4;
            int q4 = f & 15;
            int off = j * KROW + ((q4 >= 8) ? (36 + (q4 - 8) * 4) : q4 * 4);
            *(float4*)(ks + off) = Kg[f];
            *(float4*)(vs + off) = Vg[f];
        }
    }
    __syncthreads();

    // q half in regs
    float q[32];
    {
        const float4* Qg = (const float4*)(g_Q + ((size_t)b * T + row) * HS + half * 32);
#pragma unroll
        for (int h4 = 0; h4 < 8; h4++) {
            float4 v = Qg[h4];
            q[4 * h4 + 0] = v.x; q[4 * h4 + 1] = v.y;
            q[4 * h4 + 2] = v.z; q[4 * h4 + 3] = v.w;
        }
    }

    float acc[32];
#pragma unroll
    for (int h = 0; h < 32; h++) acc[h] = 0.0f;
    float l = 0.0f;
    const float log2e_scale = 1.4426950408889634f * 0.125f;
    const int base = half * 36;
    const int jmax = row | 15;    // warp-uniform upper bound

    for (int j = 0; j <= jmax; j++) {
        const float4* kr = (const float4*)(ks + j * KROW + base);
        float s0 = 0.f, s1 = 0.f, s2 = 0.f, s3 = 0.f;
#pragma unroll
        for (int h4 = 0; h4 < 8; h4++) {
            float4 kv = kr[h4];
            s0 += q[4 * h4 + 0] * kv.x;
            s1 += q[4 * h4 + 1] * kv.y;
            s2 += q[4 * h4 + 2] * kv.z;
            s3 += q[4 * h4 + 3] * kv.w;
        }
        float s = (s0 + s1) + (s2 + s3);
        s += __shfl_xor_sync(0xFFFFFFFFu, s, 1);
        float p = (j <= row) ? exp2f(s * log2e_scale) : 0.0f;
        l += p;
        const float4* vr = (const float4*)(vs + j * KROW + base);
#pragma unroll
        for (int h4 = 0; h4 < 8; h4++) {
            float4 vv = vr[h4];
            acc[4 * h4 + 0] += p * vv.x;
            acc[4 * h4 + 1] += p * vv.y;
            acc[4 * h4 + 2] += p * vv.z;
            acc[4 * h4 + 3] += p * vv.w;
        }
    }

    const float inv = 1.0f / l;
    float4* og = (float4*)(out + ((size_t)b * T + row) * HS + half * 32);
#pragma unroll
    for (int h4 = 0; h4 < 8; h4++) {
        og[h4] = make_float4(acc[4 * h4 + 0] * inv, acc[4 * h4 + 1] * inv,
                             acc[4 * h4 + 2] * inv, acc[4 * h4 + 3] * inv);
    }
}

// ---------------- launch --------------------------------------------------------
extern "C" void kernel_launch(void* const* d_in, const int* in_sizes, int n_in,
                              void* d_out, int out_size)
{
    (void)in_sizes; (void)n_in; (void)out_size;
    const float* x  = (const float*)d_in[0];
    const float* Wq = (const float*)d_in[1];
    const float* Wk = (const float*)d_in[2];
    const float* Wv = (const float*)d_in[3];
    float* out = (float*)d_out;

    convert_w<<<C, 192>>>(Wq, Wk, Wv);

    cudaFuncSetAttribute(qkv_gemm_wmma, cudaFuncAttributeMaxDynamicSharedMemorySize,
                         GEMM_SMEM_TOTAL);
    qkv_gemm_wmma<<<BT / 128, 512, GEMM_SMEM_TOTAL>>>(x);

    cudaFuncSetAttribute(attn, cudaFuncAttributeMaxDynamicSharedMemorySize,
                         ATTN_SMEM);
    attn<<<B, 512, ATTN_SMEM>>>(out);
}